// round 5
// baseline (speedup 1.0000x reference)
#include <cuda_runtime.h>
#include <cuda_bf16.h>
#include <math_constants.h>

// Problem constants
#define S_LEN 2048
#define B_SZ  64
#define D_SZ  1024

// GEMM tiling for v = h @ W  (v[b,n] = sum_e h[b,e] * W[e,n])
#define KSPLIT 16
#define KTILE  64   // D_SZ / KSPLIT
#define NTILE  64

// Scratch (device globals — no allocation allowed in kernel_launch)
__device__ float g_part[KSPLIT * B_SZ * D_SZ];   // 4 MB split-K partials
__device__ float g_v[B_SZ * D_SZ];               // 256 KB  v = h @ W
__device__ float g_energy[B_SZ * S_LEN];         // 512 KB  energies [B,S]
__device__ int   g_cnt[B_SZ];                    // per-b arrival counters (zero-init,
                                                 // self-resetting => graph-replay safe)

// ---------------------------------------------------------------------------
// Kernel 1: split-K GEMM partials. grid = (16, 16), block = 256.
// ---------------------------------------------------------------------------
__global__ __launch_bounds__(256) void gemm_partial_kernel(
    const float* __restrict__ h,   // [B, D]
    const float* __restrict__ W)   // [D, D] row-major, W[e*D + n]
{
    __shared__ float hs[KTILE * B_SZ];   // hs[e*64 + b]
    __shared__ float ws[KTILE * NTILE];  // ws[e*64 + n]

    const int nt    = blockIdx.x;
    const int ks    = blockIdx.y;
    const int tid   = threadIdx.x;
    const int ebase = ks * KTILE;
    const int nbase = nt * NTILE;

    {
        const int b  = tid >> 2;
        const int e0 = (tid & 3) * 16;
        const float* hp = h + b * D_SZ + ebase + e0;
        #pragma unroll
        for (int i = 0; i < 16; i++) hs[(e0 + i) * 64 + b] = hp[i];
    }
    {
        const int e  = tid >> 2;
        const int n0 = (tid & 3) * 16;
        const float* wp = W + (size_t)(ebase + e) * D_SZ + nbase + n0;
        #pragma unroll
        for (int i = 0; i < 16; i++) ws[e * 64 + n0 + i] = wp[i];
    }
    __syncthreads();

    const int b0 = (tid >> 4) * 4;
    const int n0 = (tid & 15) * 4;
    float acc[4][4] = {};

    #pragma unroll 8
    for (int e = 0; e < KTILE; e++) {
        const float4 hv = *(const float4*)(hs + e * 64 + b0);
        const float4 wv = *(const float4*)(ws + e * 64 + n0);
        acc[0][0] = fmaf(hv.x, wv.x, acc[0][0]);
        acc[0][1] = fmaf(hv.x, wv.y, acc[0][1]);
        acc[0][2] = fmaf(hv.x, wv.z, acc[0][2]);
        acc[0][3] = fmaf(hv.x, wv.w, acc[0][3]);
        acc[1][0] = fmaf(hv.y, wv.x, acc[1][0]);
        acc[1][1] = fmaf(hv.y, wv.y, acc[1][1]);
        acc[1][2] = fmaf(hv.y, wv.z, acc[1][2]);
        acc[1][3] = fmaf(hv.y, wv.w, acc[1][3]);
        acc[2][0] = fmaf(hv.z, wv.x, acc[2][0]);
        acc[2][1] = fmaf(hv.z, wv.y, acc[2][1]);
        acc[2][2] = fmaf(hv.z, wv.z, acc[2][2]);
        acc[2][3] = fmaf(hv.z, wv.w, acc[2][3]);
        acc[3][0] = fmaf(hv.w, wv.x, acc[3][0]);
        acc[3][1] = fmaf(hv.w, wv.y, acc[3][1]);
        acc[3][2] = fmaf(hv.w, wv.z, acc[3][2]);
        acc[3][3] = fmaf(hv.w, wv.w, acc[3][3]);
    }

    float* outp = g_part + (size_t)ks * (B_SZ * D_SZ);
    #pragma unroll
    for (int i = 0; i < 4; i++) {
        float4 r = make_float4(acc[i][0], acc[i][1], acc[i][2], acc[i][3]);
        *(float4*)(outp + (b0 + i) * D_SZ + nbase + n0) = r;
    }
}

// ---------------------------------------------------------------------------
// Kernel 2: reduce split-K partials into g_v, float4-vectorized. grid=64.
// ---------------------------------------------------------------------------
__global__ __launch_bounds__(256) void reduce_v_kernel() {
    const int idx4 = blockIdx.x * 256 + threadIdx.x;
    float4 s = make_float4(0.f, 0.f, 0.f, 0.f);
    #pragma unroll
    for (int k = 0; k < KSPLIT; k++) {
        const float4 p = *((const float4*)g_part + (size_t)k * (B_SZ * D_SZ / 4) + idx4);
        s.x += p.x; s.y += p.y; s.z += p.z; s.w += p.w;
    }
    *((float4*)g_v + idx4) = s;
}

// ---------------------------------------------------------------------------
// Kernel 3: energies[b,s] = v[b].enc[s,b] + FUSED row softmax.
// grid = (B/8 = 8, S/8 = 256), block = 256 (8 warps). Block tile 8b x 8s;
// consecutive block ids (x fastest) cover all b for one s-tile = contiguous
// 2MB of enc. Warp = one b, 8 s-rows, deferred warp reductions (8 register
// accumulators) so the 32KB of __ldcs streaming loads runs bubble-free.
// The LAST block to complete a given b (per-b atomic counter,
// threadfence-reduction pattern) has its warp do the 2048-wide softmax.
// ---------------------------------------------------------------------------
__global__ __launch_bounds__(256) void energy_kernel(const float* __restrict__ enc,
                                                     float* __restrict__ out) {
    __shared__ float vs[8][D_SZ];   // v for this block's 8 b's, 32 KB

    const int bbase = blockIdx.x * 8;
    const int sbase = blockIdx.y * 8;
    const int tid   = threadIdx.x;

    {
        const float4* src = (const float4*)(g_v + bbase * D_SZ);
        float4* dst = (float4*)&vs[0][0];
        #pragma unroll
        for (int i = 0; i < 8; i++) dst[tid + i * 256] = src[tid + i * 256];
    }
    __syncthreads();

    const int warp = tid >> 5;
    const int lane = tid & 31;
    const int b    = bbase + warp;
    const float* vp = vs[warp];

    // ---- streaming dot products: 8 rows, reductions deferred ----
    float rsum[8];
    #pragma unroll
    for (int si = 0; si < 8; si++) {
        const float4* ep =
            reinterpret_cast<const float4*>(enc + ((size_t)(sbase + si) * B_SZ + b) * D_SZ) + lane;
        float a0 = 0.f, a1 = 0.f;
        #pragma unroll
        for (int i = 0; i < 8; i += 2) {
            const float4 e0 = __ldcs(ep + i * 32);
            const float4 e1 = __ldcs(ep + (i + 1) * 32);
            const float4 v0 = *(const float4*)(vp + i * 128 + lane * 4);
            const float4 v1 = *(const float4*)(vp + (i + 1) * 128 + lane * 4);
            a0 = fmaf(e0.x, v0.x, a0); a0 = fmaf(e0.y, v0.y, a0);
            a0 = fmaf(e0.z, v0.z, a0); a0 = fmaf(e0.w, v0.w, a0);
            a1 = fmaf(e1.x, v1.x, a1); a1 = fmaf(e1.y, v1.y, a1);
            a1 = fmaf(e1.z, v1.z, a1); a1 = fmaf(e1.w, v1.w, a1);
        }
        rsum[si] = a0 + a1;
    }
    #pragma unroll
    for (int si = 0; si < 8; si++) {
        float s = rsum[si];
        #pragma unroll
        for (int o = 16; o; o >>= 1) s += __shfl_xor_sync(0xffffffffu, s, o);
        rsum[si] = s;
    }
    if (lane == 0) {
        float4 r0 = make_float4(rsum[0], rsum[1], rsum[2], rsum[3]);
        float4 r1 = make_float4(rsum[4], rsum[5], rsum[6], rsum[7]);
        *(float4*)(g_energy + b * S_LEN + sbase)     = r0;
        *(float4*)(g_energy + b * S_LEN + sbase + 4) = r1;
    }

    // ---- fused softmax: last arriving block for this b does row b ----
    __threadfence();
    unsigned last = 0;
    if (lane == 0)
        last = (atomicAdd(&g_cnt[b], 1) == (S_LEN / 8) - 1);
    last = __shfl_sync(0xffffffffu, last, 0);
    if (!last) return;

    const float4* e4 = (const float4*)(g_energy + b * S_LEN) + lane;  // 16 f4/lane

    // pass 1: max
    float m = -CUDART_INF_F;
    #pragma unroll
    for (int i = 0; i < 16; i++) {
        const float4 v = __ldcg(e4 + i * 32);
        m = fmaxf(m, fmaxf(fmaxf(v.x, v.y), fmaxf(v.z, v.w)));
    }
    #pragma unroll
    for (int o = 16; o; o >>= 1) m = fmaxf(m, __shfl_xor_sync(0xffffffffu, m, o));

    // pass 2: sum of exp
    float sum = 0.f;
    #pragma unroll
    for (int i = 0; i < 16; i++) {
        const float4 v = __ldcg(e4 + i * 32);
        sum += __expf(v.x - m) + __expf(v.y - m) + __expf(v.z - m) + __expf(v.w - m);
    }
    #pragma unroll
    for (int o = 16; o; o >>= 1) sum += __shfl_xor_sync(0xffffffffu, sum, o);
    const float inv = 1.0f / sum;

    // pass 3: write normalized
    float4* o4 = (float4*)(out + b * S_LEN) + lane;
    #pragma unroll
    for (int i = 0; i < 16; i++) {
        const float4 v = __ldcg(e4 + i * 32);
        float4 r;
        r.x = __expf(v.x - m) * inv;
        r.y = __expf(v.y - m) * inv;
        r.z = __expf(v.z - m) * inv;
        r.w = __expf(v.w - m) * inv;
        o4[i * 32] = r;
    }
    if (lane == 0) g_cnt[b] = 0;   // reset for next graph replay
}

// ---------------------------------------------------------------------------
// Launch. Inputs: hidden [1,B,D], encoder_outputs [S,B,D], W_attn [D,D],
// b_attn [D] (cancels in softmax -> unused).
// ---------------------------------------------------------------------------
extern "C" void kernel_launch(void* const* d_in, const int* in_sizes, int n_in,
                              void* d_out, int out_size) {
    const float* hidden = (const float*)d_in[0];
    const float* enc    = (const float*)d_in[1];
    const float* W      = (const float*)d_in[2];
    float* out          = (float*)d_out;

    gemm_partial_kernel<<<dim3(D_SZ / NTILE, KSPLIT), 256>>>(hidden, W);
    reduce_v_kernel<<<(B_SZ * D_SZ / 4) / 256, 256>>>();
    energy_kernel<<<dim3(B_SZ / 8, S_LEN / 8), 256>>>(enc, out);
}

// round 8
// speedup vs baseline: 1.1403x; 1.1403x over previous
#include <cuda_runtime.h>
#include <cuda_bf16.h>
#include <math_constants.h>

// Problem constants
#define S_LEN 2048
#define B_SZ  64
#define D_SZ  1024

// GEMM tiling for v = h @ W  (v[b,n] = sum_e h[b,e] * W[e,n])
#define KSPLIT 16
#define KTILE  64   // D_SZ / KSPLIT
#define NTILE  64

// Scratch (device globals — no allocation allowed in kernel_launch)
__device__ float g_part[KSPLIT * B_SZ * D_SZ];   // 4 MB split-K partials
__device__ float g_v[B_SZ * D_SZ];               // 256 KB  v = h @ W
__device__ float g_energy[B_SZ * S_LEN];         // 512 KB  energies [B,S]

// ---------------------------------------------------------------------------
// Kernel 1: split-K GEMM partials. grid = (16, 16), block = 256.
// Tile loads are exactly-coalesced float4 copies in natural layout (no
// transpose, no bank conflicts). Inner loop: 4 broadcast scalar LDS for h +
// one float4 LDS for W per e.
// ---------------------------------------------------------------------------
__global__ __launch_bounds__(256) void gemm_partial_kernel(
    const float* __restrict__ h,   // [B, D]
    const float* __restrict__ W)   // [D, D] row-major, W[e*D + n]
{
    __shared__ float hs[B_SZ][KTILE];    // hs[b][e]  16 KB
    __shared__ float ws[KTILE][NTILE];   // ws[e][n]  16 KB

    const int nt    = blockIdx.x;
    const int ks    = blockIdx.y;
    const int tid   = threadIdx.x;
    const int ebase = ks * KTILE;
    const int nbase = nt * NTILE;

    // h tile: 64 rows x 16 float4/row = 1024 float4, 4 per thread, coalesced.
    {
        const float4* h4 = (const float4*)h;
        #pragma unroll
        for (int k = 0; k < 4; k++) {
            const int idx = tid + k * 256;
            const int b = idx >> 4, c = idx & 15;
            ((float4*)&hs[b][0])[c] = h4[b * (D_SZ / 4) + (ebase >> 2) + c];
        }
    }
    // W tile: 64 rows x 16 float4/row, 4 per thread, coalesced.
    {
        const float4* W4 = (const float4*)W;
        #pragma unroll
        for (int k = 0; k < 4; k++) {
            const int idx = tid + k * 256;
            const int e = idx >> 4, c = idx & 15;
            ((float4*)&ws[e][0])[c] =
                W4[(size_t)(ebase + e) * (D_SZ / 4) + (nbase >> 2) + c];
        }
    }
    __syncthreads();

    const int b0 = (tid >> 4) * 4;
    const int n0 = (tid & 15) * 4;
    float acc[4][4] = {};

    #pragma unroll 8
    for (int e = 0; e < KTILE; e++) {
        const float4 wv = *(const float4*)&ws[e][n0];
        const float h0 = hs[b0 + 0][e];
        const float h1 = hs[b0 + 1][e];
        const float h2 = hs[b0 + 2][e];
        const float h3 = hs[b0 + 3][e];
        acc[0][0] = fmaf(h0, wv.x, acc[0][0]);
        acc[0][1] = fmaf(h0, wv.y, acc[0][1]);
        acc[0][2] = fmaf(h0, wv.z, acc[0][2]);
        acc[0][3] = fmaf(h0, wv.w, acc[0][3]);
        acc[1][0] = fmaf(h1, wv.x, acc[1][0]);
        acc[1][1] = fmaf(h1, wv.y, acc[1][1]);
        acc[1][2] = fmaf(h1, wv.z, acc[1][2]);
        acc[1][3] = fmaf(h1, wv.w, acc[1][3]);
        acc[2][0] = fmaf(h2, wv.x, acc[2][0]);
        acc[2][1] = fmaf(h2, wv.y, acc[2][1]);
        acc[2][2] = fmaf(h2, wv.z, acc[2][2]);
        acc[2][3] = fmaf(h2, wv.w, acc[2][3]);
        acc[3][0] = fmaf(h3, wv.x, acc[3][0]);
        acc[3][1] = fmaf(h3, wv.y, acc[3][1]);
        acc[3][2] = fmaf(h3, wv.z, acc[3][2]);
        acc[3][3] = fmaf(h3, wv.w, acc[3][3]);
    }

    float* outp = g_part + (size_t)ks * (B_SZ * D_SZ);
    #pragma unroll
    for (int i = 0; i < 4; i++) {
        float4 r = make_float4(acc[i][0], acc[i][1], acc[i][2], acc[i][3]);
        *(float4*)(outp + (b0 + i) * D_SZ + nbase + n0) = r;
    }
}

// ---------------------------------------------------------------------------
// Kernel 2: reduce split-K partials into g_v, float4-vectorized. grid=64.
// ---------------------------------------------------------------------------
__global__ __launch_bounds__(256) void reduce_v_kernel() {
    const int idx4 = blockIdx.x * 256 + threadIdx.x;
    float4 s = make_float4(0.f, 0.f, 0.f, 0.f);
    #pragma unroll
    for (int k = 0; k < KSPLIT; k++) {
        const float4 p = *((const float4*)g_part + (size_t)k * (B_SZ * D_SZ / 4) + idx4);
        s.x += p.x; s.y += p.y; s.z += p.z; s.w += p.w;
    }
    *((float4*)g_v + idx4) = s;
}

// ---------------------------------------------------------------------------
// Kernel 3: energies[b,s] = v[b].enc[s,b].  THE memory-bound pass (512 MB).
// grid = (B/8 = 8, S/8 = 256), block = 256 (8 warps). Block tile 8b x 8s;
// x-fastest so concurrent blocks cover a contiguous 2MB span of enc.
// Warp = one b, 8 s-rows; reductions deferred past all streaming loads.
// ---------------------------------------------------------------------------
__global__ __launch_bounds__(256) void energy_kernel(const float* __restrict__ enc) {
    __shared__ float vs[8][D_SZ];   // v for this block's 8 b's, 32 KB

    const int bbase = blockIdx.x * 8;
    const int sbase = blockIdx.y * 8;
    const int tid   = threadIdx.x;

    {
        const float4* src = (const float4*)(g_v + bbase * D_SZ);
        float4* dst = (float4*)&vs[0][0];
        #pragma unroll
        for (int i = 0; i < 8; i++) dst[tid + i * 256] = src[tid + i * 256];
    }
    __syncthreads();

    const int warp = tid >> 5;
    const int lane = tid & 31;
    const int b    = bbase + warp;
    const float* vp = vs[warp];

    float rsum[8];
    #pragma unroll
    for (int si = 0; si < 8; si++) {
        const float4* ep =
            reinterpret_cast<const float4*>(enc + ((size_t)(sbase + si) * B_SZ + b) * D_SZ) + lane;
        float a0 = 0.f, a1 = 0.f;
        #pragma unroll
        for (int i = 0; i < 8; i += 2) {
            const float4 e0 = __ldcs(ep + i * 32);
            const float4 e1 = __ldcs(ep + (i + 1) * 32);
            const float4 v0 = *(const float4*)(vp + i * 128 + lane * 4);
            const float4 v1 = *(const float4*)(vp + (i + 1) * 128 + lane * 4);
            a0 = fmaf(e0.x, v0.x, a0); a0 = fmaf(e0.y, v0.y, a0);
            a0 = fmaf(e0.z, v0.z, a0); a0 = fmaf(e0.w, v0.w, a0);
            a1 = fmaf(e1.x, v1.x, a1); a1 = fmaf(e1.y, v1.y, a1);
            a1 = fmaf(e1.z, v1.z, a1); a1 = fmaf(e1.w, v1.w, a1);
        }
        rsum[si] = a0 + a1;
    }
    #pragma unroll
    for (int si = 0; si < 8; si++) {
        float s = rsum[si];
        #pragma unroll
        for (int o = 16; o; o >>= 1) s += __shfl_xor_sync(0xffffffffu, s, o);
        rsum[si] = s;
    }
    if (lane == 0) {
        float4 r0 = make_float4(rsum[0], rsum[1], rsum[2], rsum[3]);
        float4 r1 = make_float4(rsum[4], rsum[5], rsum[6], rsum[7]);
        *(float4*)(g_energy + b * S_LEN + sbase)     = r0;
        *(float4*)(g_energy + b * S_LEN + sbase + 4) = r1;
    }
}

// ---------------------------------------------------------------------------
// Kernel 4: row softmax over S. grid = B, block = 256, 8 elems/thread.
// ---------------------------------------------------------------------------
__global__ __launch_bounds__(256) void softmax_kernel(float* __restrict__ out) {
    __shared__ float red[8];
    const int b    = blockIdx.x;
    const int tid  = threadIdx.x;
    const int warp = tid >> 5;
    const int lane = tid & 31;
    const float* e = g_energy + b * S_LEN;

    float vals[8];
    float m = -CUDART_INF_F;
    #pragma unroll
    for (int i = 0; i < 8; i++) {
        vals[i] = e[i * 256 + tid];
        m = fmaxf(m, vals[i]);
    }
    #pragma unroll
    for (int o = 16; o; o >>= 1) m = fmaxf(m, __shfl_xor_sync(0xffffffffu, m, o));
    if (lane == 0) red[warp] = m;
    __syncthreads();
    float bm = red[0];
    #pragma unroll
    for (int i = 1; i < 8; i++) bm = fmaxf(bm, red[i]);
    __syncthreads();

    float sum = 0.f;
    #pragma unroll
    for (int i = 0; i < 8; i++) {
        vals[i] = __expf(vals[i] - bm);
        sum += vals[i];
    }
    #pragma unroll
    for (int o = 16; o; o >>= 1) sum += __shfl_xor_sync(0xffffffffu, sum, o);
    if (lane == 0) red[warp] = sum;
    __syncthreads();
    float tot = 0.f;
    #pragma unroll
    for (int i = 0; i < 8; i++) tot += red[i];
    const float inv = 1.0f / tot;

    #pragma unroll
    for (int i = 0; i < 8; i++)
        out[b * S_LEN + i * 256 + tid] = vals[i] * inv;
}

// ---------------------------------------------------------------------------
// Launch. Inputs: hidden [1,B,D], encoder_outputs [S,B,D], W_attn [D,D],
// b_attn [D] (cancels in softmax -> unused).
// ---------------------------------------------------------------------------
extern "C" void kernel_launch(void* const* d_in, const int* in_sizes, int n_in,
                              void* d_out, int out_size) {
    const float* hidden = (const float*)d_in[0];
    const float* enc    = (const float*)d_in[1];
    const float* W      = (const float*)d_in[2];
    float* out          = (float*)d_out;

    gemm_partial_kernel<<<dim3(D_SZ / NTILE, KSPLIT), 256>>>(hidden, W);
    reduce_v_kernel<<<(B_SZ * D_SZ / 4) / 256, 256>>>();
    energy_kernel<<<dim3(B_SZ / 8, S_LEN / 8), 256>>>(enc);
    softmax_kernel<<<B_SZ, 256>>>(out);
}